// round 5
// baseline (speedup 1.0000x reference)
#include <cuda_runtime.h>
#include <cuda_bf16.h>

// Shapes (known): N=100000, E=3200000, F_IN=128, H=16, C=2
#define MAXN 100000
#define MAXE 3200000
#define SCAN_B 1024

// Static scratch (allocation-free; zero-initialized at module load).
// INVARIANT: d_cnt is all-zero on entry to kernel_launch (k_out re-zeros it).
__device__ int    d_cnt[MAXN];       // in-degree (excl self loop)
__device__ int    d_off[MAXN];       // CSR row offsets (by dst)
__device__ int    d_cur[MAXN];       // fill cursors
__device__ int    d_srclist[MAXE];   // CSR column indices (src per dst-bucket)
__device__ int    d_bsum[256];       // scan block sums
__device__ float  d_dinv[MAXN];
__device__ float4 d_g1[MAXN * 4];    // g1[i] = (x@W1)[i]*dinv[i], 16 f32/node
__device__ float2 d_g2[MAXN];        // g2[i] = (h1@W2)[i]*dinv[i]

// ---------------------------------------------------------------------------
// L0: count in-degrees (d_cnt starts zeroed by invariant)
__global__ void k_count(const int* __restrict__ dst, int E) {
    int e = blockIdx.x * blockDim.x + threadIdx.x;
    if (e < E) atomicAdd(&d_cnt[dst[e]], 1);
}

// L1: block-local exclusive scan; also dinv = rsqrt(deg+1)
__global__ void k_scan1(int N) {
    __shared__ int s[SCAN_B];
    int i = blockIdx.x * SCAN_B + threadIdx.x;
    int v = (i < N) ? d_cnt[i] : 0;
    s[threadIdx.x] = v;
    __syncthreads();
#pragma unroll
    for (int d = 1; d < SCAN_B; d <<= 1) {
        int t = (threadIdx.x >= d) ? s[threadIdx.x - d] : 0;
        __syncthreads();
        s[threadIdx.x] += t;
        __syncthreads();
    }
    if (i < N) {
        d_off[i]  = s[threadIdx.x] - v;      // block-local exclusive
        d_dinv[i] = rsqrtf((float)(v + 1));  // self loop adds 1
    }
    if (threadIdx.x == SCAN_B - 1) d_bsum[blockIdx.x] = s[SCAN_B - 1];
}

// L2: GEMM1 (needs only dinv): 4 threads/node, butterfly reduce
__global__ void k_gemm1(const float* __restrict__ x,
                        const float* __restrict__ W1, int N) {
    __shared__ float4 W1s[128 * 4];  // W1[k][j] as float4 over j
    for (int i = threadIdx.x; i < 512; i += blockDim.x)
        W1s[i] = ((const float4*)W1)[i];
    __syncthreads();

    int t = blockIdx.x * blockDim.x + threadIdx.x;
    int node = t >> 2;
    if (node >= N) return;
    int part = t & 3;

    float acc[16];
#pragma unroll
    for (int j = 0; j < 16; j++) acc[j] = 0.0f;

    const float4* x4 = (const float4*)x + (size_t)node * 32 + part * 8;
#pragma unroll
    for (int k4 = 0; k4 < 8; k4++) {
        float4 xv = __ldg(&x4[k4]);
        int kb = part * 32 + k4 * 4;
#pragma unroll
        for (int kk = 0; kk < 4; kk++) {
            float xs = (kk == 0) ? xv.x : (kk == 1) ? xv.y : (kk == 2) ? xv.z : xv.w;
#pragma unroll
            for (int j4 = 0; j4 < 4; j4++) {
                float4 w = W1s[(kb + kk) * 4 + j4];
                acc[j4 * 4 + 0] += xs * w.x;
                acc[j4 * 4 + 1] += xs * w.y;
                acc[j4 * 4 + 2] += xs * w.z;
                acc[j4 * 4 + 3] += xs * w.w;
            }
        }
    }
#pragma unroll
    for (int j = 0; j < 16; j++) {
        acc[j] += __shfl_xor_sync(0xffffffffu, acc[j], 1);
        acc[j] += __shfl_xor_sync(0xffffffffu, acc[j], 2);
    }
    float dv = d_dinv[node];
    float4 g = make_float4(acc[part * 4 + 0] * dv, acc[part * 4 + 1] * dv,
                           acc[part * 4 + 2] * dv, acc[part * 4 + 3] * dv);
    d_g1[node * 4 + part] = g;
}

// L3: finish scan (each block redundantly prefixes d_bsum) + init cursors
__global__ void k_scan3(int N, int nb) {
    __shared__ int base_s;
    if (threadIdx.x == 0) {
        int run = 0;
        int b = (int)blockIdx.x;
        for (int q = 0; q < b; q++) run += d_bsum[q];
        base_s = run;
    }
    __syncthreads();
    int i = blockIdx.x * SCAN_B + threadIdx.x;
    if (i < N) {
        int o = d_off[i] + base_s;
        d_off[i] = o;
        d_cur[i] = o;
    }
}

// L4: bucket-fill CSR column list
__global__ void k_fill(const int* __restrict__ src,
                       const int* __restrict__ dst, int E) {
    int e = blockIdx.x * blockDim.x + threadIdx.x;
    if (e >= E) return;
    int p = atomicAdd(&d_cur[dst[e]], 1);
    d_srclist[p] = src[e];
}

// L5: gather layer 1 + fused layer-2 GEMM. WARP PER NODE.
// Lane = 4*g + p: group g in [0,8) handles edge (k+g), part p holds float4 p.
__global__ void k_gather1(const float* __restrict__ b1,
                          const float* __restrict__ W2, int N) {
    int warp = (blockIdx.x * blockDim.x + threadIdx.x) >> 5;
    if (warp >= N) return;
    int node = warp;
    int lane = threadIdx.x & 31;
    int grp  = lane >> 2;
    int part = lane & 3;

    int off = d_off[node];
    int deg = d_cnt[node];

    float4 a = make_float4(0.f, 0.f, 0.f, 0.f);
    for (int k = 0; k < deg; k += 8) {
        int e = k + grp;
        if (e < deg) {
            int s = __ldg(&d_srclist[off + e]);
            float4 g = d_g1[s * 4 + part];
            a.x += g.x; a.y += g.y; a.z += g.z; a.w += g.w;
        }
    }
    // reduce part-p partial sums across the 8 groups
#pragma unroll
    for (int o = 4; o <= 16; o <<= 1) {
        a.x += __shfl_xor_sync(0xffffffffu, a.x, o);
        a.y += __shfl_xor_sync(0xffffffffu, a.y, o);
        a.z += __shfl_xor_sync(0xffffffffu, a.z, o);
        a.w += __shfl_xor_sync(0xffffffffu, a.w, o);
    }
    // self loop
    float4 sl = d_g1[node * 4 + part];
    a.x += sl.x; a.y += sl.y; a.z += sl.z; a.w += sl.w;

    float dv = d_dinv[node];
    float4 bb = __ldg(&((const float4*)b1)[part]);
    float h0 = fmaxf(a.x * dv + bb.x, 0.0f);
    float h1 = fmaxf(a.y * dv + bb.y, 0.0f);
    float h2 = fmaxf(a.z * dv + bb.z, 0.0f);
    float h3 = fmaxf(a.w * dv + bb.w, 0.0f);

    int jb = part * 4;
    float o0 = h0 * __ldg(&W2[(jb + 0) * 2 + 0]) + h1 * __ldg(&W2[(jb + 1) * 2 + 0])
             + h2 * __ldg(&W2[(jb + 2) * 2 + 0]) + h3 * __ldg(&W2[(jb + 3) * 2 + 0]);
    float o1 = h0 * __ldg(&W2[(jb + 0) * 2 + 1]) + h1 * __ldg(&W2[(jb + 1) * 2 + 1])
             + h2 * __ldg(&W2[(jb + 2) * 2 + 1]) + h3 * __ldg(&W2[(jb + 3) * 2 + 1]);

    o0 += __shfl_xor_sync(0xffffffffu, o0, 1);
    o0 += __shfl_xor_sync(0xffffffffu, o0, 2);
    o1 += __shfl_xor_sync(0xffffffffu, o1, 1);
    o1 += __shfl_xor_sync(0xffffffffu, o1, 2);

    if (lane == 0) d_g2[node] = make_float2(o0 * dv, o1 * dv);
}

// L6: gather layer 2 + bias. WARP PER NODE (lane = edge). Also re-zeros d_cnt
// for the next call (keeps the entry invariant).
__global__ void k_out(const float* __restrict__ b2, float2* __restrict__ out,
                      int N) {
    int warp = (blockIdx.x * blockDim.x + threadIdx.x) >> 5;
    if (warp >= N) return;
    int node = warp;
    int lane = threadIdx.x & 31;

    int off = d_off[node];
    int deg = d_cnt[node];

    float ax = 0.f, ay = 0.f;
    for (int k = lane; k < deg; k += 32) {
        int s = __ldg(&d_srclist[off + k]);
        float2 g = d_g2[s];
        ax += g.x; ay += g.y;
    }
#pragma unroll
    for (int o = 1; o <= 16; o <<= 1) {
        ax += __shfl_xor_sync(0xffffffffu, ax, o);
        ay += __shfl_xor_sync(0xffffffffu, ay, o);
    }
    if (lane == 0) {
        float2 sl = d_g2[node];
        float dv = d_dinv[node];
        out[node] = make_float2((ax + sl.x) * dv + __ldg(&b2[0]),
                                (ay + sl.y) * dv + __ldg(&b2[1]));
        d_cnt[node] = 0;  // reset for next replay
    }
}

// ---------------------------------------------------------------------------
extern "C" void kernel_launch(void* const* d_in, const int* in_sizes, int n_in,
                              void* d_out, int out_size) {
    const float* x  = (const float*)d_in[0];
    const int*   ei = (const int*)d_in[1];   // int32 [2, E]
    const float* W1 = (const float*)d_in[2];
    const float* b1 = (const float*)d_in[3];
    const float* W2 = (const float*)d_in[4];
    const float* b2 = (const float*)d_in[5];

    int N = in_sizes[0] / 128;
    int E = in_sizes[1] / 2;
    const int* src = ei;
    const int* dst = ei + E;
    int nb = (N + SCAN_B - 1) / SCAN_B;

    k_count<<<(E + 255) / 256, 256>>>(dst, E);                 // launch 0
    k_scan1<<<nb, SCAN_B>>>(N);                                // launch 1
    k_gemm1<<<(4 * N + 255) / 256, 256>>>(x, W1, N);           // launch 2
    k_scan3<<<nb, SCAN_B>>>(N, nb);                            // launch 3
    k_fill<<<(E + 255) / 256, 256>>>(src, dst, E);             // launch 4
    k_gather1<<<(32 * N + 255) / 256, 256>>>(b1, W2, N);       // launch 5 (profiled)
    k_out<<<(32 * N + 255) / 256, 256>>>(b2, (float2*)d_out, N); // launch 6
}

// round 6
// speedup vs baseline: 1.1152x; 1.1152x over previous
#include <cuda_runtime.h>
#include <cuda_bf16.h>

// Shapes (known): N=100000, E=3200000, F_IN=128, H=16, C=2
#define MAXN 100000
#define MAXE 3200000

// Static scratch (allocation-free; zero-initialized at module load).
// INVARIANT: d_cnt is all-zero on entry to kernel_launch (k_final re-zeros it).
__device__ int    d_cnt[MAXN];       // in-degree (excl self loop)
__device__ float  d_dinv[MAXN];
__device__ float4 d_g1  [MAXN * 4];  // g1[i] = (x@W1)[i]*dinv[i]
__device__ float4 d_acc1[MAXN * 4];  // init = g1[i] (self loop), then RED-add
__device__ float2 d_g2  [MAXN];
__device__ float2 d_acc2[MAXN];

// L0: integer in-degree count
__global__ void k_count(const int* __restrict__ dst, int E) {
    int e = blockIdx.x * blockDim.x + threadIdx.x;
    if (e < E) atomicAdd(&d_cnt[dst[e]], 1);
}

// L1: dinv = rsqrt(deg+1)  (self loop)
__global__ void k_dinv(int N) {
    int i = blockIdx.x * blockDim.x + threadIdx.x;
    if (i < N) d_dinv[i] = rsqrtf((float)(d_cnt[i] + 1));
}

// L2: g1[i] = (x[i]@W1)*dinv[i]; acc1[i] = g1[i]. 4 threads/node.
__global__ void k_gemm1(const float* __restrict__ x,
                        const float* __restrict__ W1, int N) {
    __shared__ float4 W1s[128 * 4];  // W1[k][j] as float4 over j
    for (int i = threadIdx.x; i < 512; i += blockDim.x)
        W1s[i] = ((const float4*)W1)[i];
    __syncthreads();

    int t = blockIdx.x * blockDim.x + threadIdx.x;
    int node = t >> 2;
    if (node >= N) return;
    int part = t & 3;

    float acc[16];
#pragma unroll
    for (int j = 0; j < 16; j++) acc[j] = 0.0f;

    const float4* x4 = (const float4*)x + (size_t)node * 32 + part * 8;
#pragma unroll
    for (int k4 = 0; k4 < 8; k4++) {
        float4 xv = __ldg(&x4[k4]);
        int kb = part * 32 + k4 * 4;
#pragma unroll
        for (int kk = 0; kk < 4; kk++) {
            float xs = (kk == 0) ? xv.x : (kk == 1) ? xv.y : (kk == 2) ? xv.z : xv.w;
#pragma unroll
            for (int j4 = 0; j4 < 4; j4++) {
                float4 w = W1s[(kb + kk) * 4 + j4];
                acc[j4 * 4 + 0] += xs * w.x;
                acc[j4 * 4 + 1] += xs * w.y;
                acc[j4 * 4 + 2] += xs * w.z;
                acc[j4 * 4 + 3] += xs * w.w;
            }
        }
    }
#pragma unroll
    for (int j = 0; j < 16; j++) {
        acc[j] += __shfl_xor_sync(0xffffffffu, acc[j], 1);
        acc[j] += __shfl_xor_sync(0xffffffffu, acc[j], 2);
    }
    float dv = d_dinv[node];
    float4 g = make_float4(acc[part * 4 + 0] * dv, acc[part * 4 + 1] * dv,
                           acc[part * 4 + 2] * dv, acc[part * 4 + 3] * dv);
    d_g1[node * 4 + part]   = g;
    d_acc1[node * 4 + part] = g;
}

// L3 (PROFILED SLOT): scatter layer 1 — 4 lanes/edge, one red.v4 each.
__global__ void k_scatter1(const int* __restrict__ src,
                           const int* __restrict__ dst, int E) {
    int t = blockIdx.x * blockDim.x + threadIdx.x;
    int e = t >> 2;
    if (e >= E) return;
    int part = t & 3;
    int s = src[e];
    int d = dst[e];
    float4 g = d_g1[s * 4 + part];
    float* p = (float*)&d_acc1[d * 4 + part];
    asm volatile("red.global.add.v4.f32 [%0], {%1,%2,%3,%4};"
                 :: "l"(p), "f"(g.x), "f"(g.y), "f"(g.z), "f"(g.w)
                 : "memory");
}

// L4: h1 = relu(dinv*acc1 + b1); g2 = (h1@W2)*dinv; acc2 = g2
__global__ void k_layer2_gemm(const float* __restrict__ b1,
                              const float* __restrict__ W2, int N) {
    int i = blockIdx.x * blockDim.x + threadIdx.x;
    if (i >= N) return;
    float dv = d_dinv[i];
    float o0 = 0.0f, o1 = 0.0f;
#pragma unroll
    for (int j4 = 0; j4 < 4; j4++) {
        float4 a = d_acc1[i * 4 + j4];
        float4 bb = __ldg(&((const float4*)b1)[j4]);
#pragma unroll
        for (int kk = 0; kk < 4; kk++) {
            int j = j4 * 4 + kk;
            float av = (kk == 0) ? a.x : (kk == 1) ? a.y : (kk == 2) ? a.z : a.w;
            float bv = (kk == 0) ? bb.x : (kk == 1) ? bb.y : (kk == 2) ? bb.z : bb.w;
            float h = fmaxf(av * dv + bv, 0.0f);
            o0 += h * __ldg(&W2[j * 2 + 0]);
            o1 += h * __ldg(&W2[j * 2 + 1]);
        }
    }
    float2 g = make_float2(o0 * dv, o1 * dv);
    d_g2[i]   = g;
    d_acc2[i] = g;
}

// L5: scatter layer 2 — one thread/edge, one red.v2
__global__ void k_scatter2(const int* __restrict__ src,
                           const int* __restrict__ dst, int E) {
    int e = blockIdx.x * blockDim.x + threadIdx.x;
    if (e >= E) return;
    float2 g = d_g2[src[e]];
    float* p = (float*)&d_acc2[dst[e]];
    asm volatile("red.global.add.v2.f32 [%0], {%1,%2};"
                 :: "l"(p), "f"(g.x), "f"(g.y)
                 : "memory");
}

// L6: out[i] = dinv[i]*acc2[i] + b2; also re-zero d_cnt for next replay.
__global__ void k_final(const float* __restrict__ b2, float2* __restrict__ out,
                        int N) {
    int i = blockIdx.x * blockDim.x + threadIdx.x;
    if (i >= N) return;
    float dv = d_dinv[i];
    float2 a = d_acc2[i];
    out[i] = make_float2(a.x * dv + __ldg(&b2[0]), a.y * dv + __ldg(&b2[1]));
    d_cnt[i] = 0;
}

extern "C" void kernel_launch(void* const* d_in, const int* in_sizes, int n_in,
                              void* d_out, int out_size) {
    const float* x  = (const float*)d_in[0];
    const int*   ei = (const int*)d_in[1];   // int32 [2, E]
    const float* W1 = (const float*)d_in[2];
    const float* b1 = (const float*)d_in[3];
    const float* W2 = (const float*)d_in[4];
    const float* b2 = (const float*)d_in[5];

    int N = in_sizes[0] / 128;
    int E = in_sizes[1] / 2;
    const int* src = ei;
    const int* dst = ei + E;

    k_count<<<(E + 255) / 256, 256>>>(dst, E);                   // 0
    k_dinv<<<(N + 255) / 256, 256>>>(N);                         // 1
    k_gemm1<<<(4 * N + 255) / 256, 256>>>(x, W1, N);             // 2
    {
        long long t = 4LL * E;
        k_scatter1<<<(int)((t + 255) / 256), 256>>>(src, dst, E); // 3 (profiled)
    }
    k_layer2_gemm<<<(N + 255) / 256, 256>>>(b1, W2, N);          // 4
    k_scatter2<<<(E + 255) / 256, 256>>>(src, dst, E);           // 5
    k_final<<<(N + 255) / 256, 256>>>(b2, (float2*)d_out, N);    // 6
}

// round 7
// speedup vs baseline: 1.1766x; 1.0551x over previous
#include <cuda_runtime.h>
#include <cuda_bf16.h>

// Shapes (known): N=100000, E=3200000, F_IN=128, H=16, C=2
#define MAXN 100000
#define MAXE 3200000

// Static scratch (allocation-free; zero-initialized at module load).
// INVARIANT: d_cnt is all-zero on entry to kernel_launch (k_final re-zeros it).
__device__ int    d_cnt[MAXN];       // in-degree (excl self loop)
__device__ float  d_dinv[MAXN];
__device__ float4 d_g1  [MAXN * 4];  // raw x@W1, then scaled by dinv
__device__ float4 d_acc1[MAXN * 4];  // init = g1[i]*dinv (self loop), RED target
__device__ float2 d_g2  [MAXN];
__device__ float2 d_acc2[MAXN];

// ---------------------------------------------------------------------------
// K0: role-split fused kernel.
//   Blocks [0, gemmBlocks)            : raw GEMM1 -> d_g1 (UNSCALED)
//   Blocks [gemmBlocks, +countBlocks) : in-degree count -> d_cnt
__global__ void k_gemm_count(const float* __restrict__ x,
                             const float* __restrict__ W1,
                             const int* __restrict__ dst,
                             int N, int E, int gemmBlocks) {
    if ((int)blockIdx.x >= gemmBlocks) {
        // ---- count role ----
        int e = (blockIdx.x - gemmBlocks) * blockDim.x + threadIdx.x;
        if (e < E) atomicAdd(&d_cnt[dst[e]], 1);
        return;
    }
    // ---- gemm role: 4 threads per node ----
    __shared__ float4 W1s[128 * 4];  // W1[k][j] as float4 over j
    for (int i = threadIdx.x; i < 512; i += blockDim.x)
        W1s[i] = ((const float4*)W1)[i];
    __syncthreads();

    int t = blockIdx.x * blockDim.x + threadIdx.x;
    int node = t >> 2;
    if (node >= N) return;
    int part = t & 3;

    float acc[16];
#pragma unroll
    for (int j = 0; j < 16; j++) acc[j] = 0.0f;

    const float4* x4 = (const float4*)x + (size_t)node * 32 + part * 8;
#pragma unroll
    for (int k4 = 0; k4 < 8; k4++) {
        float4 xv = __ldg(&x4[k4]);
        int kb = part * 32 + k4 * 4;
#pragma unroll
        for (int kk = 0; kk < 4; kk++) {
            float xs = (kk == 0) ? xv.x : (kk == 1) ? xv.y : (kk == 2) ? xv.z : xv.w;
#pragma unroll
            for (int j4 = 0; j4 < 4; j4++) {
                float4 w = W1s[(kb + kk) * 4 + j4];
                acc[j4 * 4 + 0] += xs * w.x;
                acc[j4 * 4 + 1] += xs * w.y;
                acc[j4 * 4 + 2] += xs * w.z;
                acc[j4 * 4 + 3] += xs * w.w;
            }
        }
    }
#pragma unroll
    for (int j = 0; j < 16; j++) {
        acc[j] += __shfl_xor_sync(0xffffffffu, acc[j], 1);
        acc[j] += __shfl_xor_sync(0xffffffffu, acc[j], 2);
    }
    d_g1[node * 4 + part] = make_float4(acc[part * 4 + 0], acc[part * 4 + 1],
                                        acc[part * 4 + 2], acc[part * 4 + 3]);
}

// K1: dinv = rsqrt(cnt+1); g1 *= dinv; acc1 = g1. 4 threads/node.
__global__ void k_scale(int N) {
    int t = blockIdx.x * blockDim.x + threadIdx.x;
    int node = t >> 2;
    if (node >= N) return;
    int part = t & 3;
    float dv = rsqrtf((float)(d_cnt[node] + 1));
    if (part == 0) d_dinv[node] = dv;
    float4 g = d_g1[node * 4 + part];
    g.x *= dv; g.y *= dv; g.z *= dv; g.w *= dv;
    d_g1[node * 4 + part]   = g;
    d_acc1[node * 4 + part] = g;
}

// K2: scatter layer 1 — 4 lanes/edge, one red.v4 each.
__global__ void k_scatter1(const int* __restrict__ src,
                           const int* __restrict__ dst, int E) {
    int t = blockIdx.x * blockDim.x + threadIdx.x;
    int e = t >> 2;
    if (e >= E) return;
    int part = t & 3;
    int s = __ldg(&src[e]);
    int d = __ldg(&dst[e]);
    float4 g = d_g1[s * 4 + part];
    float* p = (float*)&d_acc1[d * 4 + part];
    asm volatile("red.global.add.v4.f32 [%0], {%1,%2,%3,%4};"
                 :: "l"(p), "f"(g.x), "f"(g.y), "f"(g.z), "f"(g.w)
                 : "memory");
}

// K3 (PROFILED SLOT): h1 = relu(dinv*acc1 + b1); g2 = (h1@W2)*dinv; acc2 = g2
__global__ void k_layer2_gemm(const float* __restrict__ b1,
                              const float* __restrict__ W2, int N) {
    int i = blockIdx.x * blockDim.x + threadIdx.x;
    if (i >= N) return;
    float dv = d_dinv[i];
    float o0 = 0.0f, o1 = 0.0f;
#pragma unroll
    for (int j4 = 0; j4 < 4; j4++) {
        float4 a = d_acc1[i * 4 + j4];
        float4 bb = __ldg(&((const float4*)b1)[j4]);
#pragma unroll
        for (int kk = 0; kk < 4; kk++) {
            int j = j4 * 4 + kk;
            float av = (kk == 0) ? a.x : (kk == 1) ? a.y : (kk == 2) ? a.z : a.w;
            float bv = (kk == 0) ? bb.x : (kk == 1) ? bb.y : (kk == 2) ? bb.z : bb.w;
            float h = fmaxf(av * dv + bv, 0.0f);
            o0 += h * __ldg(&W2[j * 2 + 0]);
            o1 += h * __ldg(&W2[j * 2 + 1]);
        }
    }
    float2 g = make_float2(o0 * dv, o1 * dv);
    d_g2[i]   = g;
    d_acc2[i] = g;
}

// K4: scatter layer 2 — one thread/edge, one red.v2
__global__ void k_scatter2(const int* __restrict__ src,
                           const int* __restrict__ dst, int E) {
    int e = blockIdx.x * blockDim.x + threadIdx.x;
    if (e >= E) return;
    float2 g = d_g2[__ldg(&src[e])];
    float* p = (float*)&d_acc2[__ldg(&dst[e])];
    asm volatile("red.global.add.v2.f32 [%0], {%1,%2};"
                 :: "l"(p), "f"(g.x), "f"(g.y)
                 : "memory");
}

// K5: out[i] = dinv[i]*acc2[i] + b2; re-zero d_cnt for next replay.
__global__ void k_final(const float* __restrict__ b2, float2* __restrict__ out,
                        int N) {
    int i = blockIdx.x * blockDim.x + threadIdx.x;
    if (i >= N) return;
    float dv = d_dinv[i];
    float2 a = d_acc2[i];
    out[i] = make_float2(a.x * dv + __ldg(&b2[0]), a.y * dv + __ldg(&b2[1]));
    d_cnt[i] = 0;
}

// ---------------------------------------------------------------------------
extern "C" void kernel_launch(void* const* d_in, const int* in_sizes, int n_in,
                              void* d_out, int out_size) {
    const float* x  = (const float*)d_in[0];
    const int*   ei = (const int*)d_in[1];   // int32 [2, E]
    const float* W1 = (const float*)d_in[2];
    const float* b1 = (const float*)d_in[3];
    const float* W2 = (const float*)d_in[4];
    const float* b2 = (const float*)d_in[5];

    int N = in_sizes[0] / 128;
    int E = in_sizes[1] / 2;
    const int* src = ei;
    const int* dst = ei + E;

    int gemmBlocks  = (4 * N + 255) / 256;
    int countBlocks = (E + 255) / 256;

    k_gemm_count<<<gemmBlocks + countBlocks, 256>>>(x, W1, dst, N, E, gemmBlocks); // 0
    k_scale<<<(4 * N + 255) / 256, 256>>>(N);                                      // 1
    {
        long long t = 4LL * E;
        k_scatter1<<<(int)((t + 255) / 256), 256>>>(src, dst, E);                  // 2
    }
    k_layer2_gemm<<<(N + 255) / 256, 256>>>(b1, W2, N);                            // 3 (profiled)
    k_scatter2<<<(E + 255) / 256, 256>>>(src, dst, E);                             // 4
    k_final<<<(N + 255) / 256, 256>>>(b2, (float2*)d_out, N);                      // 5
}